// round 9
// baseline (speedup 1.0000x reference)
#include <cuda_runtime.h>

#define NEG_INF __int_as_float(0xff800000)
#define SMEM_ATTN ((32*132 + 128*132 + 128*132 + 32*132)*4)

// scratch (each symbol < 2GB)
__device__ float g_q[(size_t)4096*32*512];     // [b,q,h*d]
__device__ float g_k[(size_t)4096*128*512];    // [b,e,h*d]
__device__ float g_v[(size_t)4096*128*512];    // [b,e,h*d]
__device__ float g_attn[(size_t)4096*32*512];  // [b,q,h*d]

__device__ __forceinline__ float to_tf32(float x){
    float y; asm("cvt.rna.tf32.f32 %0, %1;" : "=f"(y) : "f"(x)); return y;
}
__device__ __forceinline__ float4 tf4(float4 v){
    v.x=to_tf32(v.x); v.y=to_tf32(v.y); v.z=to_tf32(v.z); v.w=to_tf32(v.w); return v;
}
__device__ __forceinline__ void mma8(float c[4], unsigned a0,unsigned a1,unsigned a2,unsigned a3,
                                     unsigned b0,unsigned b1){
    asm volatile("mma.sync.aligned.m16n8k8.row.col.f32.tf32.tf32.f32 "
                 "{%0,%1,%2,%3},{%4,%5,%6,%7},{%8,%9},{%0,%1,%2,%3};\n"
                 : "+f"(c[0]),"+f"(c[1]),"+f"(c[2]),"+f"(c[3])
                 : "r"(a0),"r"(a1),"r"(a2),"r"(a3),"r"(b0),"r"(b1));
}

// C[M,Nd] = A[M,Kd] @ B[Nd,Kd]^T.  128x128 tile, 8 warps, warp tile 32x64.
// QKV=true: A=Ap(entities), outputs routed to g_q/g_k/g_v (Q rows e>=32 skipped).
// QKV=false: A=g_attn, C=Cp with bias + row-mask epilogue.
// rmask: 4-byte elements (int32 or fp32 bool) — nonzero word == True.
template<bool QKV>
__global__ __launch_bounds__(256,2)
void gemm_tn(const float* __restrict__ Ap, const float* __restrict__ B,
             float* __restrict__ Cp, int Kd, int Nd,
             const float* __restrict__ bias, const unsigned* __restrict__ rmask)
{
    __shared__ float sA[128*36], sB[128*36];
    const float* A = QKV ? Ap : g_attn;
    int tid=threadIdx.x, warp=tid>>5, lane=tid&31, g=lane>>2, t=lane&3;
    int m0=blockIdx.y*128, n0=blockIdx.x*128;
    int r0=(warp>>1)*32, nw=(warp&1)*64;
    float acc[2][8][4];
    #pragma unroll
    for(int a=0;a<2;a++){ for(int j=0;j<8;j++){ for(int q=0;q<4;q++) acc[a][j][q]=0.f; } }

    for(int kc=0;kc<Kd;kc+=32){
        __syncthreads();
        #pragma unroll
        for(int u=0;u<4;u++){
            int i=tid+u*256, r=i>>3, c4=(i&7)*4;
            *(float4*)&sA[r*36+c4] = tf4(*(const float4*)&A[(size_t)(m0+r)*Kd + kc + c4]);
            *(float4*)&sB[r*36+c4] = tf4(*(const float4*)&B[(size_t)(n0+r)*Kd + kc + c4]);
        }
        __syncthreads();
        #pragma unroll
        for(int ks=0;ks<4;ks++){
            int k0=ks*8;
            unsigned a[2][4];
            #pragma unroll
            for(int rb=0;rb<2;rb++){
                int r=r0+rb*16+g;
                a[rb][0]=__float_as_uint(sA[r*36+k0+t]);
                a[rb][1]=__float_as_uint(sA[(r+8)*36+k0+t]);
                a[rb][2]=__float_as_uint(sA[r*36+k0+4+t]);
                a[rb][3]=__float_as_uint(sA[(r+8)*36+k0+4+t]);
            }
            #pragma unroll
            for(int j=0;j<8;j++){
                int n=nw+j*8+g;
                unsigned b0=__float_as_uint(sB[n*36+k0+t]);
                unsigned b1=__float_as_uint(sB[n*36+k0+4+t]);
                mma8(acc[0][j],a[0][0],a[0][1],a[0][2],a[0][3],b0,b1);
                mma8(acc[1][j],a[1][0],a[1][1],a[1][2],a[1][3],b0,b1);
            }
        }
    }
    #pragma unroll
    for(int rb=0;rb<2;rb++){
        #pragma unroll
        for(int j=0;j<8;j++){
            int n=n0+nw+j*8+2*t;
            float b0v=0.f,b1v=0.f;
            if(!QKV && bias){ b0v=bias[n]; b1v=bias[n+1]; }
            #pragma unroll
            for(int h2=0;h2<2;h2++){
                int r=m0+r0+rb*16+g+h2*8;
                float x0=acc[rb][j][h2*2]+b0v, x1=acc[rb][j][h2*2+1]+b1v;
                if(QKV){
                    int e=r&127, bb=r>>7;
                    float2 v; v.x=x0; v.y=x1;
                    if(n<512){ if(e<32) *(float2*)&g_q[((size_t)(bb*32+e))*512+n]=v; }
                    else if(n<1024) *(float2*)&g_k[(size_t)r*512+(n-512)]=v;
                    else            *(float2*)&g_v[(size_t)r*512+(n-1024)]=v;
                } else {
                    if(rmask[r]!=0u){ x0=0.f; x1=0.f; }
                    float2 v; v.x=x0; v.y=x1;
                    *(float2*)&Cp[(size_t)r*Nd+n]=v;
                }
            }
        }
    }
}

// One CTA per (batch, head). 512 thr = 16 warps, warp tile 16x16.
__global__ __launch_bounds__(512,1)
void attn_kernel(const unsigned* __restrict__ pmask)
{
    extern __shared__ float sm[];
    float* sQ  = sm;                 // 32x132
    float* sK  = sQ  + 32*132;       // 128x132
    float* sVt = sK  + 128*132;      // 128x132  (V transposed: [d][e])
    float* sL  = sVt + 128*132;      // 32x132   (logits, then P)
    int b=blockIdx.x, h=blockIdx.y;
    int tid=threadIdx.x, warp=tid>>5, lane=tid&31, g=lane>>2, t=lane&3;
    const float* Qg = g_q + ((size_t)b*32 )*512 + h*128;
    const float* Kg = g_k + ((size_t)b*128)*512 + h*128;
    const float* Vg = g_v + ((size_t)b*128)*512 + h*128;

    #pragma unroll
    for(int u=0;u<2;u++){                     // Q: 32x128
        int i=tid+u*512, r=i>>5, c4=(i&31)*4;
        *(float4*)&sQ[r*132+c4] = tf4(*(const float4*)&Qg[(size_t)r*512+c4]);
    }
    #pragma unroll
    for(int u=0;u<8;u++){                     // K: 128x128
        int i=tid+u*512, r=i>>5, c4=(i&31)*4;
        *(float4*)&sK[r*132+c4] = tf4(*(const float4*)&Kg[(size_t)r*512+c4]);
    }
    #pragma unroll
    for(int u=0;u<32;u++){                    // V^T: scalar transpose
        int i=tid+u*512, e=i>>7, d=i&127;
        sVt[d*132+e] = to_tf32(Vg[(size_t)e*512+d]);
    }
    __syncthreads();

    int r0=(warp>>3)*16, n0=(warp&7)*16;
    // ---- logits = Q @ K^T ----
    float cl[2][4]={};
    #pragma unroll
    for(int kk=0;kk<16;kk++){
        int k0=kk*8, r=r0+g;
        unsigned a0=__float_as_uint(sQ[r*132+k0+t]);
        unsigned a1=__float_as_uint(sQ[(r+8)*132+k0+t]);
        unsigned a2=__float_as_uint(sQ[r*132+k0+4+t]);
        unsigned a3=__float_as_uint(sQ[(r+8)*132+k0+4+t]);
        #pragma unroll
        for(int j=0;j<2;j++){
            int n=n0+j*8+g;
            unsigned b0=__float_as_uint(sK[n*132+k0+t]);
            unsigned b1=__float_as_uint(sK[n*132+k0+4+t]);
            mma8(cl[j],a0,a1,a2,a3,b0,b1);
        }
    }
    const float scale=0.08838834764831845f;   // 1/sqrt(128)
    const unsigned* pm = pmask + (size_t)b*32*128;
    #pragma unroll
    for(int j=0;j<2;j++){
        int n=n0+j*8+2*t;
        #pragma unroll
        for(int h2=0;h2<2;h2++){
            int r=r0+g+h2*8;
            float x0=cl[j][h2*2]*scale, x1=cl[j][h2*2+1]*scale;
            if(pm[r*128+n  ]!=0u) x0=NEG_INF;
            if(pm[r*128+n+1]!=0u) x1=NEG_INF;
            sL[r*132+n]=x0; sL[r*132+n+1]=x1;
        }
    }
    __syncthreads();
    // ---- softmax: 2 rows per warp ----
    #pragma unroll
    for(int rr=0;rr<2;rr++){
        int r=warp*2+rr;
        float x[4];
        #pragma unroll
        for(int i2=0;i2<4;i2++) x[i2]=sL[r*132+lane+32*i2];
        float m=fmaxf(fmaxf(x[0],x[1]),fmaxf(x[2],x[3]));
        #pragma unroll
        for(int o=16;o>0;o>>=1) m=fmaxf(m,__shfl_xor_sync(0xffffffffu,m,o));
        bool dead=(m==NEG_INF);
        float p[4], s=0.f;
        #pragma unroll
        for(int i2=0;i2<4;i2++){ p[i2]=dead?0.f:__expf(x[i2]-m); s+=p[i2]; }
        #pragma unroll
        for(int o=16;o>0;o>>=1) s+=__shfl_xor_sync(0xffffffffu,s,o);
        float inv=(s>0.f)?(1.f/s):0.f;
        #pragma unroll
        for(int i2=0;i2<4;i2++) sL[r*132+lane+32*i2]=to_tf32(p[i2]*inv);
    }
    __syncthreads();
    // ---- out = P @ V ----
    float co[2][4]={};
    #pragma unroll
    for(int kk=0;kk<16;kk++){
        int k0=kk*8, r=r0+g;
        unsigned a0=__float_as_uint(sL[r*132+k0+t]);
        unsigned a1=__float_as_uint(sL[(r+8)*132+k0+t]);
        unsigned a2=__float_as_uint(sL[r*132+k0+4+t]);
        unsigned a3=__float_as_uint(sL[(r+8)*132+k0+4+t]);
        #pragma unroll
        for(int j=0;j<2;j++){
            int n=n0+j*8+g;
            unsigned b0=__float_as_uint(sVt[n*132+k0+t]);
            unsigned b1=__float_as_uint(sVt[n*132+k0+4+t]);
            mma8(co[j],a0,a1,a2,a3,b0,b1);
        }
    }
    #pragma unroll
    for(int j=0;j<2;j++){
        int n=n0+j*8+2*t;
        #pragma unroll
        for(int h2=0;h2<2;h2++){
            int r=r0+g+h2*8;
            float2 v; v.x=co[j][h2*2]; v.y=co[j][h2*2+1];
            *(float2*)&g_attn[((size_t)b*32+r)*512 + h*128 + n]=v;
        }
    }
}

extern "C" void kernel_launch(void* const* d_in, const int* in_sizes, int n_in,
                              void* d_out, int out_size)
{
    const float*    ent   = (const float*)d_in[0];
    const unsigned* pmask = (const unsigned*)d_in[1];   // bool as 4-byte words
    const unsigned* post  = (const unsigned*)d_in[2];   // bool as 4-byte words
    const float*    Win   = (const float*)d_in[3];
    const float*    Wout  = (const float*)d_in[4];
    const float*    bout  = (const float*)d_in[5];
    float*          out   = (float*)d_out;
    (void)in_sizes; (void)n_in; (void)out_size;

    cudaFuncSetAttribute(attn_kernel, cudaFuncAttributeMaxDynamicSharedMemorySize, SMEM_ATTN);

    // K1: QKV projection  [524288 x 256] @ [1536 x 256]^T
    gemm_tn<true ><<<dim3(12,4096),256>>>(ent, Win, nullptr, 256, 1536, nullptr, nullptr);
    // K2: per-(batch,head) masked attention
    attn_kernel<<<dim3(4096,4),512,SMEM_ATTN>>>(pmask);
    // K3: out projection   [131072 x 512] @ [512 x 512]^T + bias, post-mask
    gemm_tn<false><<<dim3(4,1024),256>>>(nullptr, Wout, out, 512, 512, bout, post);
}

// round 10
// speedup vs baseline: 1.4016x; 1.4016x over previous
#include <cuda_runtime.h>

#define NEG_INF __int_as_float(0xff800000)
#define SMEM_ATTN ((32*132 + 128*132 + 128*128 + 32*132)*4)
#define SMEM_GEMM (2*2*128*36*4)   // 2 stages x (A,B) x 128x36 fp32 = 73728

__device__ float g_q[(size_t)4096*32*512];
__device__ float g_k[(size_t)4096*128*512];
__device__ float g_v[(size_t)4096*128*512];
__device__ float g_attn[(size_t)4096*32*512];

__device__ __forceinline__ float to_tf32(float x){
    float y; asm("cvt.rna.tf32.f32 %0, %1;" : "=f"(y) : "f"(x)); return y;
}
__device__ __forceinline__ unsigned tfu(float x){ return __float_as_uint(to_tf32(x)); }
__device__ __forceinline__ float4 tf4(float4 v){
    v.x=to_tf32(v.x); v.y=to_tf32(v.y); v.z=to_tf32(v.z); v.w=to_tf32(v.w); return v;
}
__device__ __forceinline__ void mma8(float c[4], unsigned a0,unsigned a1,unsigned a2,unsigned a3,
                                     unsigned b0,unsigned b1){
    asm volatile("mma.sync.aligned.m16n8k8.row.col.f32.tf32.tf32.f32 "
                 "{%0,%1,%2,%3},{%4,%5,%6,%7},{%8,%9},{%0,%1,%2,%3};\n"
                 : "+f"(c[0]),"+f"(c[1]),"+f"(c[2]),"+f"(c[3])
                 : "r"(a0),"r"(a1),"r"(a2),"r"(a3),"r"(b0),"r"(b1));
}
__device__ __forceinline__ void cpa16(float* d, const float* s){
    unsigned a=(unsigned)__cvta_generic_to_shared(d);
    asm volatile("cp.async.ca.shared.global [%0], [%1], 16;\n" :: "r"(a),"l"(s));
}

// MODE 0: KV  (A=entities, B=Win+512*256, Nd=1024 -> g_k/g_v)
// MODE 1: Q   (A=entities gathered rows b*32+q,   Nd=512 -> g_q)
// MODE 2: OUT (A=g_attn, B=Wout, Nd=512, bias+rowmask -> Cp)
// 128 threads, CTA tile 128x128, warp tile 64x64, cp.async 2-stage.
template<int MODE,int KD>
__device__ __forceinline__ void issue_tile(const float* __restrict__ A,
                                           const float* __restrict__ B,
                                           float* sm, int m0,int n0,int rbl,int c4,
                                           int kc,int s)
{
    float* dA = sm + s*9216;
    float* dB = dA + 4608;
    #pragma unroll
    for(int u=0;u<8;u++){
        int row = rbl + u*16;
        const float* as;
        if(MODE==1){ int rr=m0+row; as = A + ((size_t)(rr>>5)*128 + (rr&31))*256 + kc + c4; }
        else if(MODE==0){ as = A + (size_t)(m0+row)*256 + kc + c4; }
        else { as = g_attn + (size_t)(m0+row)*512 + kc + c4; }
        cpa16(&dA[row*36+c4], as);
        cpa16(&dB[row*36+c4], B + (size_t)(n0+row)*KD + kc + c4);
    }
    asm volatile("cp.async.commit_group;\n" ::: "memory");
}

template<int MODE,int KD>
__global__ __launch_bounds__(128,2)
void gemm2(const float* __restrict__ A, const float* __restrict__ B,
           float* __restrict__ Cp, const float* __restrict__ bias,
           const unsigned* __restrict__ rmask)
{
    extern __shared__ float sm[];
    const int tid=threadIdx.x, warp=tid>>5, lane=tid&31, g=lane>>2, t=lane&3;
    const int m0=blockIdx.y*128, n0=blockIdx.x*128;
    const int wr=(warp>>1)*64, wc=(warp&1)*64;
    const int rbl=tid>>3, c4=(tid&7)*4;
    float acc[4][8][4];
    #pragma unroll
    for(int a_=0;a_<4;a_++){ for(int j=0;j<8;j++){ for(int q=0;q<4;q++) acc[a_][j][q]=0.f; } }

    const int NK = KD/32;
    issue_tile<MODE,KD>(A,B,sm,m0,n0,rbl,c4,0,0);
    for(int kc=0;kc<NK;kc++){
        if(kc+1<NK){
            issue_tile<MODE,KD>(A,B,sm,m0,n0,rbl,c4,(kc+1)*32,(kc+1)&1);
            asm volatile("cp.async.wait_group 1;\n" ::: "memory");
        } else {
            asm volatile("cp.async.wait_group 0;\n" ::: "memory");
        }
        __syncthreads();
        const float* sA = sm + (kc&1)*9216;
        const float* sB = sA + 4608;
        #pragma unroll
        for(int ks=0;ks<4;ks++){
            int k0=ks*8;
            unsigned a[4][4];
            #pragma unroll
            for(int rb=0;rb<4;rb++){
                int r=wr+rb*16+g;
                a[rb][0]=tfu(sA[r*36+k0+t]);
                a[rb][1]=tfu(sA[(r+8)*36+k0+t]);
                a[rb][2]=tfu(sA[r*36+k0+4+t]);
                a[rb][3]=tfu(sA[(r+8)*36+k0+4+t]);
            }
            #pragma unroll
            for(int j=0;j<8;j++){
                int n=wc+j*8+g;
                unsigned b0=tfu(sB[n*36+k0+t]);
                unsigned b1=tfu(sB[n*36+k0+4+t]);
                #pragma unroll
                for(int rb=0;rb<4;rb++)
                    mma8(acc[rb][j],a[rb][0],a[rb][1],a[rb][2],a[rb][3],b0,b1);
            }
        }
        __syncthreads();
    }
    #pragma unroll
    for(int rb=0;rb<4;rb++){
      #pragma unroll
      for(int j=0;j<8;j++){
        int n=n0+wc+j*8+2*t;
        float b0v=0.f,b1v=0.f;
        if(MODE==2){ b0v=bias[n]; b1v=bias[n+1]; }
        #pragma unroll
        for(int h2=0;h2<2;h2++){
            int r=m0+wr+rb*16+g+h2*8;
            float2 v; v.x=acc[rb][j][h2*2]+b0v; v.y=acc[rb][j][h2*2+1]+b1v;
            if(MODE==0){
                if(n<512) *(float2*)&g_k[(size_t)r*512+n]=v;
                else      *(float2*)&g_v[(size_t)r*512+(n-512)]=v;
            } else if(MODE==1){
                *(float2*)&g_q[(size_t)r*512+n]=v;
            } else {
                if(rmask[r]!=0u){ v.x=0.f; v.y=0.f; }
                *(float2*)&Cp[(size_t)r*512+n]=v;
            }
        }
      }
    }
}

// One CTA per (batch, head). 512 thr = 16 warps, warp tile 16x16.
__global__ __launch_bounds__(512,1)
void attn_kernel(const unsigned* __restrict__ pmask)
{
    extern __shared__ float sm[];
    float* sQ = sm;                  // 32x132
    float* sK = sQ + 32*132;         // 128x132
    float* sV = sK + 128*132;        // 128x128, natural [e][d], XOR-swizzled cols
    float* sL = sV + 128*128;        // 32x132
    int b=blockIdx.x, h=blockIdx.y;
    int tid=threadIdx.x, warp=tid>>5, lane=tid&31, g=lane>>2, t=lane&3;
    const float* Qg = g_q + ((size_t)b*32 )*512 + h*128;
    const float* Kg = g_k + ((size_t)b*128)*512 + h*128;
    const float* Vg = g_v + ((size_t)b*128)*512 + h*128;

    #pragma unroll
    for(int u=0;u<2;u++){
        int i=tid+u*512, r=i>>5, c4=(i&31)*4;
        *(float4*)&sQ[r*132+c4] = tf4(*(const float4*)&Qg[(size_t)r*512+c4]);
    }
    #pragma unroll
    for(int u=0;u<8;u++){
        int i=tid+u*512, r=i>>5, c4=(i&31)*4;
        *(float4*)&sK[r*132+c4] = tf4(*(const float4*)&Kg[(size_t)r*512+c4]);
    }
    #pragma unroll
    for(int u=0;u<8;u++){
        int i=tid+u*512, k=i>>5, c4=(i&31)*4;
        *(float4*)&sV[k*128 + (c4 ^ ((k&3)<<3))] = tf4(*(const float4*)&Vg[(size_t)k*512+c4]);
    }
    __syncthreads();

    int r0=(warp>>3)*16, n0=(warp&7)*16;
    // ---- logits = Q @ K^T ----
    float cl[2][4]={};
    #pragma unroll
    for(int kk=0;kk<16;kk++){
        int k0=kk*8, r=r0+g;
        unsigned a0=__float_as_uint(sQ[r*132+k0+t]);
        unsigned a1=__float_as_uint(sQ[(r+8)*132+k0+t]);
        unsigned a2=__float_as_uint(sQ[r*132+k0+4+t]);
        unsigned a3=__float_as_uint(sQ[(r+8)*132+k0+4+t]);
        #pragma unroll
        for(int j=0;j<2;j++){
            int n=n0+j*8+g;
            unsigned b0=__float_as_uint(sK[n*132+k0+t]);
            unsigned b1=__float_as_uint(sK[n*132+k0+4+t]);
            mma8(cl[j],a0,a1,a2,a3,b0,b1);
        }
    }
    const float scale=0.08838834764831845f;
    const unsigned* pm = pmask + (size_t)b*32*128;
    #pragma unroll
    for(int j=0;j<2;j++){
        int n=n0+j*8+2*t;
        #pragma unroll
        for(int h2=0;h2<2;h2++){
            int r=r0+g+h2*8;
            float x0=cl[j][h2*2]*scale, x1=cl[j][h2*2+1]*scale;
            if(pm[r*128+n  ]!=0u) x0=NEG_INF;
            if(pm[r*128+n+1]!=0u) x1=NEG_INF;
            sL[r*132+n]=x0; sL[r*132+n+1]=x1;
        }
    }
    __syncthreads();
    // ---- softmax: 2 rows per warp ----
    #pragma unroll
    for(int rr=0;rr<2;rr++){
        int r=warp*2+rr;
        float x[4];
        #pragma unroll
        for(int i2=0;i2<4;i2++) x[i2]=sL[r*132+lane+32*i2];
        float m=fmaxf(fmaxf(x[0],x[1]),fmaxf(x[2],x[3]));
        #pragma unroll
        for(int o=16;o>0;o>>=1) m=fmaxf(m,__shfl_xor_sync(0xffffffffu,m,o));
        bool dead=(m==NEG_INF);
        float p[4], s=0.f;
        #pragma unroll
        for(int i2=0;i2<4;i2++){ p[i2]=dead?0.f:__expf(x[i2]-m); s+=p[i2]; }
        #pragma unroll
        for(int o=16;o>0;o>>=1) s+=__shfl_xor_sync(0xffffffffu,s,o);
        float inv=(s>0.f)?(1.f/s):0.f;
        #pragma unroll
        for(int i2=0;i2<4;i2++) sL[r*132+lane+32*i2]=to_tf32(p[i2]*inv);
    }
    __syncthreads();
    // ---- out = P @ V (V natural layout, swizzled B-fragment) ----
    float co[2][4]={};
    #pragma unroll
    for(int kk=0;kk<16;kk++){
        int k0=kk*8, r=r0+g;
        unsigned a0=__float_as_uint(sL[r*132+k0+t]);
        unsigned a1=__float_as_uint(sL[(r+8)*132+k0+t]);
        unsigned a2=__float_as_uint(sL[r*132+k0+4+t]);
        unsigned a3=__float_as_uint(sL[(r+8)*132+k0+4+t]);
        #pragma unroll
        for(int j=0;j<2;j++){
            int n=(n0+j*8+g) ^ (t<<3);
            unsigned b0=__float_as_uint(sV[(k0+t  )*128 + n]);
            unsigned b1=__float_as_uint(sV[(k0+4+t)*128 + n]);
            mma8(co[j],a0,a1,a2,a3,b0,b1);
        }
    }
    #pragma unroll
    for(int j=0;j<2;j++){
        int n=n0+j*8+2*t;
        #pragma unroll
        for(int h2=0;h2<2;h2++){
            int r=r0+g+h2*8;
            float2 v; v.x=co[j][h2*2]; v.y=co[j][h2*2+1];
            *(float2*)&g_attn[((size_t)b*32+r)*512 + h*128 + n]=v;
        }
    }
}

extern "C" void kernel_launch(void* const* d_in, const int* in_sizes, int n_in,
                              void* d_out, int out_size)
{
    const float*    ent   = (const float*)d_in[0];
    const unsigned* pmask = (const unsigned*)d_in[1];
    const unsigned* post  = (const unsigned*)d_in[2];
    const float*    Win   = (const float*)d_in[3];
    const float*    Wout  = (const float*)d_in[4];
    const float*    bout  = (const float*)d_in[5];
    float*          out   = (float*)d_out;
    (void)in_sizes; (void)n_in; (void)out_size;

    cudaFuncSetAttribute(gemm2<0,256>, cudaFuncAttributeMaxDynamicSharedMemorySize, SMEM_GEMM);
    cudaFuncSetAttribute(gemm2<1,256>, cudaFuncAttributeMaxDynamicSharedMemorySize, SMEM_GEMM);
    cudaFuncSetAttribute(gemm2<2,512>, cudaFuncAttributeMaxDynamicSharedMemorySize, SMEM_GEMM);
    cudaFuncSetAttribute(attn_kernel,  cudaFuncAttributeMaxDynamicSharedMemorySize, SMEM_ATTN);

    // K1a: K/V projection  [524288 x 1024] = ent @ (Win rows 512..1535)^T
    gemm2<0,256><<<dim3(8,4096),128,SMEM_GEMM>>>(ent, Win + 512*256, nullptr, nullptr, nullptr);
    // K1b: Q projection    [131072 x 512]  = ent[b,0:32] @ (Win rows 0..511)^T
    gemm2<1,256><<<dim3(4,1024),128,SMEM_GEMM>>>(ent, Win, nullptr, nullptr, nullptr);
    // K2: per-(batch,head) masked attention
    attn_kernel<<<dim3(4096,4),512,SMEM_ATTN>>>(pmask);
    // K3: out projection   [131072 x 512] @ Wout^T + bias, post-mask
    gemm2<2,512><<<dim3(4,1024),128,SMEM_GEMM>>>(nullptr, Wout, out, bout, post);
}